// round 3
// baseline (speedup 1.0000x reference)
#include <cuda_runtime.h>

#define NPOS        22743
#define NB          64
#define CELLS_PER_B 7581            // 76*76 + 38*38 + 19*19
#define BLK         256
#define BX          30              // ceil(7581/256)
#define TOTAL_BLOCKS (BX * NB)

// Accumulators: [0]=n_obj  [1]=s_xy  [2]=s_wh  [3]=s_cls  [4]=s_obj(weighted)
__device__ float        g_acc[5];
__device__ unsigned int g_cnt;

// ANCHORS / stride, stride = 608/grid = {8,16,32} (exact in fp32)
__constant__ float c_anch[3][3][2] = {
    {{1.25f, 1.625f},  {2.0f,   3.75f},   {4.125f,    2.875f}},
    {{1.875f,2.8125f}, {3.875f, 2.8125f}, {3.6875f,   7.4375f}},
    {{3.625f,2.8125f}, {4.875f, 6.1875f}, {11.65625f, 10.1875f}},
};

// bce(sigmoid(z), t) = softplus(z) - t*z
__device__ __forceinline__ float softplusf(float z) {
    return __logf(1.0f + __expf(z));
}

// streaming (evict-first) scalar load
__device__ __forceinline__ float ldcs(const float* p) { return __ldcs(p); }

__global__ void __launch_bounds__(BLK)
yolo_loss_kernel(const float* __restrict__ x, const float* __restrict__ t,
                 float* __restrict__ out) {
    const int cell = blockIdx.x * BLK + threadIdx.x;
    const int b    = blockIdx.y;

    float a_n = 0.f, a_xy = 0.f, a_wh = 0.f, a_cls = 0.f, a_obj = 0.f;

    if (cell < CELLS_PER_B) {
        int sc, p0;
        float g, wobj;
        if (cell < 5776) {                    // 76x76
            sc = 0; p0 = cell * 3;                     g = 76.f; wobj = 1.f / 1108992.f;
        } else if (cell < 7220) {             // 38x38
            sc = 1; p0 = 17328 + (cell - 5776) * 3;    g = 38.f; wobj = 1.f / 277248.f;
        } else {                              // 19x19
            sc = 2; p0 = 21660 + (cell - 7220) * 3;    g = 19.f; wobj = 1.f / 69312.f;
        }

        const size_t base = ((size_t)b * NPOS + p0) * 85;
        const float* __restrict__ tb = t + base;
        const float* __restrict__ xb = x + base;

        float inter[3], d[3], t2r[3], t3r[3], t4v[3], x4v[3];
        #pragma unroll
        for (int j = 0; j < 3; j++) {
            const float* tp = tb + j * 85;
            t2r[j] = ldcs(tp + 2);
            t3r[j] = ldcs(tp + 3);
            t4v[j] = ldcs(tp + 4);
            x4v[j] = ldcs(xb + j * 85 + 4);
            float tw = t2r[j] * g, th = t3r[j] * g;
            float aw = c_anch[sc][j][0], ah = c_anch[sc][j][1];
            float in_ = fminf(tw, aw) * fminf(th, ah);
            inter[j] = in_;
            d[j]     = tw * th + aw * ah - in_ + 1e-12f;   // union + eps, > 0
        }

        // argmax of inter[j]/d[j] via cross-mult (d > 0); first-occurrence tie-break
        int best = 0;
        float ib = inter[0], db = d[0];
        if (inter[1] * db > ib * d[1]) { best = 1; ib = inter[1]; db = d[1]; }
        if (inter[2] * db > ib * d[2]) { best = 2; }

        #pragma unroll
        for (int j = 0; j < 3; j++) {
            bool keep = (inter[j] <= 0.7f * d[j]) || (j == best);

            // s = bce(sigmoid(x4), t4) = softplus(x4) - t4*x4
            float s = softplusf(x4v[j]) - t4v[j] * x4v[j];

            // obj: keep ? s : bce(sigmoid(0), 0) = ln 2
            a_obj += wobj * (keep ? s : 0.69314718055994531f);

            if (t4v[j] > 0.0f) {              // ~2% of positions
                const float* tp = tb + j * 85;
                const float* xp = xb + j * 85;
                a_n   += 1.0f;
                a_cls += s;

                float x0 = ldcs(xp + 0), x1 = ldcs(xp + 1);
                float x2 = ldcs(xp + 2), x3 = ldcs(xp + 3);
                float t0 = ldcs(tp + 0), t1 = ldcs(tp + 1);

                // xy: bce(sigmoid(x), t)
                a_xy += (softplusf(x0) - t0 * x0) + (softplusf(x1) - t1 * x1);

                // wh: bce(clip(x, eps, 1-eps), t)  [1-eps rounds to 1.0f in fp32]
                float p2 = fmaxf(x2, 1e-12f);
                float p3 = fmaxf(x3, 1e-12f);
                a_wh += -(t2r[j] * __logf(p2) + (1.0f - t2r[j]) * __logf(1.0f - p2));
                a_wh += -(t3r[j] * __logf(p3) + (1.0f - t3r[j]) * __logf(1.0f - p3));
            }
        }
    }

    // ---- reduction: warp shuffle -> shared -> global atomics ----
    #pragma unroll
    for (int o = 16; o > 0; o >>= 1) {
        a_n   += __shfl_down_sync(0xFFFFFFFFu, a_n,   o);
        a_xy  += __shfl_down_sync(0xFFFFFFFFu, a_xy,  o);
        a_wh  += __shfl_down_sync(0xFFFFFFFFu, a_wh,  o);
        a_cls += __shfl_down_sync(0xFFFFFFFFu, a_cls, o);
        a_obj += __shfl_down_sync(0xFFFFFFFFu, a_obj, o);
    }

    __shared__ float sh[5];
    if (threadIdx.x < 5) sh[threadIdx.x] = 0.0f;
    __syncthreads();
    if ((threadIdx.x & 31) == 0) {
        atomicAdd(&sh[0], a_n);
        atomicAdd(&sh[1], a_xy);
        atomicAdd(&sh[2], a_wh);
        atomicAdd(&sh[3], a_cls);
        atomicAdd(&sh[4], a_obj);
    }
    __syncthreads();
    if (threadIdx.x < 5) atomicAdd(&g_acc[threadIdx.x], sh[threadIdx.x]);

    // ---- last block finalizes and resets state for the next graph replay ----
    if (threadIdx.x == 0) {
        __threadfence();
        unsigned int done = atomicAdd(&g_cnt, 1u);
        if (done == TOTAL_BLOCKS - 1) {
            float vn   = atomicAdd(&g_acc[0], 0.f);
            float vxy  = atomicAdd(&g_acc[1], 0.f);
            float vwh  = atomicAdd(&g_acc[2], 0.f);
            float vcls = atomicAdd(&g_acc[3], 0.f);
            float vobj = atomicAdd(&g_acc[4], 0.f);
            float n = fmaxf(vn, 1.0f);
            out[0] = (vxy + vwh) / (2.0f * n) + vcls / n + vobj;
            atomicExch(&g_acc[0], 0.f);
            atomicExch(&g_acc[1], 0.f);
            atomicExch(&g_acc[2], 0.f);
            atomicExch(&g_acc[3], 0.f);
            atomicExch(&g_acc[4], 0.f);
            atomicExch(&g_cnt, 0u);
        }
    }
}

extern "C" void kernel_launch(void* const* d_in, const int* in_sizes, int n_in,
                              void* d_out, int out_size) {
    const float* x = (const float*)d_in[0];
    const float* t = (const float*)d_in[1];
    float* out = (float*)d_out;

    dim3 grid(BX, NB);
    yolo_loss_kernel<<<grid, BLK>>>(x, t, out);
}

// round 5
// speedup vs baseline: 1.0121x; 1.0121x over previous
#include <cuda_runtime.h>

#define NPOS        22743
#define NB          64
#define CELLS_PER_B 7581            // 76*76 + 38*38 + 19*19
#define BLK         256
#define BX          30              // ceil(7581/256)
#define TOTAL_BLOCKS (BX * NB)

// Accumulators: [0]=n_obj  [1]=s_xy  [2]=s_wh  [3]=s_cls  [4]=s_obj(weighted)
__device__ float        g_acc[5];
__device__ unsigned int g_cnt;

// ANCHORS / stride, stride = 608/grid = {8,16,32} (exact in fp32)
__constant__ float c_anch[3][3][2] = {
    {{1.25f, 1.625f},  {2.0f,   3.75f},   {4.125f,    2.875f}},
    {{1.875f,2.8125f}, {3.875f, 2.8125f}, {3.6875f,   7.4375f}},
    {{3.625f,2.8125f}, {4.875f, 6.1875f}, {11.65625f, 10.1875f}},
};

// bce(sigmoid(z), t) = softplus(z) - t*z
__device__ __forceinline__ float softplusf(float z) {
    return __logf(1.0f + __expf(z));
}

__device__ __forceinline__ float4 ldg4(const float* p) {
    return __ldg(reinterpret_cast<const float4*>(p));
}

// extract 5 consecutive floats starting at lane r (0..3) of the 8-lane pair (v0,v1)
__device__ __forceinline__ void extract5(float4 v0, float4 v1, int r,
                                         float& e0, float& e1, float& e2,
                                         float& e3, float& e4) {
    switch (r) {
    case 0:  e0=v0.x; e1=v0.y; e2=v0.z; e3=v0.w; e4=v1.x; break;
    case 1:  e0=v0.y; e1=v0.z; e2=v0.w; e3=v1.x; e4=v1.y; break;
    case 2:  e0=v0.z; e1=v0.w; e2=v1.x; e3=v1.y; e4=v1.z; break;
    default: e0=v0.w; e1=v1.x; e2=v1.y; e3=v1.z; e4=v1.w; break;
    }
}

// lane r of a float4 (SEL chain, no branch)
__device__ __forceinline__ float lane(float4 v, int r) {
    float e = (r == 0) ? v.x : (r == 1) ? v.y : (r == 2) ? v.z : v.w;
    return e;
}

__global__ void __launch_bounds__(BLK)
yolo_loss_kernel(const float* __restrict__ x, const float* __restrict__ t,
                 float* __restrict__ out) {
    const int cell = blockIdx.x * BLK + threadIdx.x;
    const int b    = blockIdx.y;

    float a_n = 0.f, a_xy = 0.f, a_wh = 0.f, a_cls = 0.f, a_obj = 0.f;

    if (cell < CELLS_PER_B) {
        int sc, p0;
        float g, wobj;
        if (cell < 5776) {                    // 76x76
            sc = 0; p0 = cell * 3;                     g = 76.f; wobj = 1.f / 1108992.f;
        } else if (cell < 7220) {             // 38x38
            sc = 1; p0 = 17328 + (cell - 5776) * 3;    g = 38.f; wobj = 1.f / 277248.f;
        } else {                              // 19x19
            sc = 2; p0 = 21660 + (cell - 7220) * 3;    g = 19.f; wobj = 1.f / 69312.f;
        }

        const size_t base = ((size_t)b * NPOS + p0) * 85;

        // Per-row aligned bases and phases; batch all 9 LDG.128 up-front.
        size_t a0[3]; int rr[3];
        float4 tv0[3], tv1[3], xv1[3];
        #pragma unroll
        for (int j = 0; j < 3; j++) {
            size_t off = base + (size_t)j * 85;
            a0[j] = off & ~(size_t)3;          // 16B-aligned
            rr[j] = (int)(off & 3);
            tv0[j] = ldg4(t + a0[j]);          // floats a0..a0+3
            tv1[j] = ldg4(t + a0[j] + 4);      // floats a0+4..a0+7
            xv1[j] = ldg4(x + a0[j] + 4);      // contains x4 (lane rr)
        }

        float t0v[3], t1v[3], t2v[3], t3v[3], t4v[3], x4v[3];
        float inter[3], d[3];
        #pragma unroll
        for (int j = 0; j < 3; j++) {
            extract5(tv0[j], tv1[j], rr[j], t0v[j], t1v[j], t2v[j], t3v[j], t4v[j]);
            x4v[j] = lane(xv1[j], rr[j]);
            float tw = t2v[j] * g, th = t3v[j] * g;
            float aw = c_anch[sc][j][0], ah = c_anch[sc][j][1];
            float in_ = fminf(tw, aw) * fminf(th, ah);
            inter[j] = in_;
            d[j]     = tw * th + aw * ah - in_ + 1e-12f;   // union + eps, > 0
        }

        // argmax of inter[j]/d[j] via cross-mult (d > 0); first-occurrence tie-break
        int best = 0;
        float ib = inter[0], db = d[0];
        if (inter[1] * db > ib * d[1]) { best = 1; ib = inter[1]; db = d[1]; }
        if (inter[2] * db > ib * d[2]) { best = 2; }

        #pragma unroll
        for (int j = 0; j < 3; j++) {
            bool keep = (inter[j] <= 0.7f * d[j]) || (j == best);

            // s = bce(sigmoid(x4), t4) = softplus(x4) - t4*x4
            float s = softplusf(x4v[j]) - t4v[j] * x4v[j];

            // obj: keep ? s : bce(sigmoid(0), 0) = ln 2
            a_obj += wobj * (keep ? s : 0.69314718055994531f);

            if (t4v[j] > 0.0f) {              // ~2% of positions
                float4 xv0 = ldg4(x + a0[j]);  // floats a0..a0+3
                float x0, x1, x2, x3, xu;
                extract5(xv0, xv1[j], rr[j], x0, x1, x2, x3, xu);
                (void)xu;
                a_n   += 1.0f;
                a_cls += s;

                // xy: bce(sigmoid(x), t)
                a_xy += (softplusf(x0) - t0v[j] * x0)
                      + (softplusf(x1) - t1v[j] * x1);

                // wh: bce(clip(x, eps, 1-eps), t)  [1-eps rounds to 1.0f in fp32]
                float p2 = fmaxf(x2, 1e-12f);
                float p3 = fmaxf(x3, 1e-12f);
                a_wh += -(t2v[j] * __logf(p2) + (1.0f - t2v[j]) * __logf(1.0f - p2));
                a_wh += -(t3v[j] * __logf(p3) + (1.0f - t3v[j]) * __logf(1.0f - p3));
            }
        }
    }

    // ---- reduction: warp shuffle -> shared -> global atomics ----
    #pragma unroll
    for (int o = 16; o > 0; o >>= 1) {
        a_n   += __shfl_down_sync(0xFFFFFFFFu, a_n,   o);
        a_xy  += __shfl_down_sync(0xFFFFFFFFu, a_xy,  o);
        a_wh  += __shfl_down_sync(0xFFFFFFFFu, a_wh,  o);
        a_cls += __shfl_down_sync(0xFFFFFFFFu, a_cls, o);
        a_obj += __shfl_down_sync(0xFFFFFFFFu, a_obj, o);
    }

    __shared__ float sh[5];
    if (threadIdx.x < 5) sh[threadIdx.x] = 0.0f;
    __syncthreads();
    if ((threadIdx.x & 31) == 0) {
        atomicAdd(&sh[0], a_n);
        atomicAdd(&sh[1], a_xy);
        atomicAdd(&sh[2], a_wh);
        atomicAdd(&sh[3], a_cls);
        atomicAdd(&sh[4], a_obj);
    }
    __syncthreads();
    if (threadIdx.x < 5) atomicAdd(&g_acc[threadIdx.x], sh[threadIdx.x]);

    // ---- last block finalizes and resets state for the next graph replay ----
    if (threadIdx.x == 0) {
        __threadfence();
        unsigned int done = atomicAdd(&g_cnt, 1u);
        if (done == TOTAL_BLOCKS - 1) {
            float vn   = atomicAdd(&g_acc[0], 0.f);
            float vxy  = atomicAdd(&g_acc[1], 0.f);
            float vwh  = atomicAdd(&g_acc[2], 0.f);
            float vcls = atomicAdd(&g_acc[3], 0.f);
            float vobj = atomicAdd(&g_acc[4], 0.f);
            float n = fmaxf(vn, 1.0f);
            out[0] = (vxy + vwh) / (2.0f * n) + vcls / n + vobj;
            atomicExch(&g_acc[0], 0.f);
            atomicExch(&g_acc[1], 0.f);
            atomicExch(&g_acc[2], 0.f);
            atomicExch(&g_acc[3], 0.f);
            atomicExch(&g_acc[4], 0.f);
            atomicExch(&g_cnt, 0u);
        }
    }
}

extern "C" void kernel_launch(void* const* d_in, const int* in_sizes, int n_in,
                              void* d_out, int out_size) {
    const float* x = (const float*)d_in[0];
    const float* t = (const float*)d_in[1];
    float* out = (float*)d_out;

    dim3 grid(BX, NB);
    yolo_loss_kernel<<<grid, BLK>>>(x, t, out);
}